// round 15
// baseline (speedup 1.0000x reference)
#include <cuda_runtime.h>
#include <cuda_bf16.h>

#define DD 128
#define HH 512
#define WW 512
#define THRESH 0.997f
#define KPK 131072
#define NB  65536                 // value buckets AND spatial cells (16*64*64)
#define NCH 64                    // rank-kernel blocks / chunks of 1024 buckets
#define CSLOTS 16                 // per-cell candidate capacity (lambda~1.5 -> safe)
#define BSLOTS 16                 // per-bucket peak capacity (lambda~1.2 -> safe)
#define CAND_CAP (1<<18)          // 262144

// ------------- device scratch (static; all counters self-restore to 0) --------
__device__ unsigned c_cnt[NB];                // per-cell count   (zeroed by rank)
__device__ uint2    c_data[NB * CSLOTS];      // (idx, valbits) per cell slot
__device__ unsigned g_ncand;                  // compact count    (zeroed by rank)
__device__ uint2    g_cand[CAND_CAP];         // compact candidate list (idx, valbits)
__device__ unsigned g_hist[NB];               // per-bucket peak count (zeroed by rank)
__device__ unsigned b_sidx[NB * BSLOTS];      // voxel idx per bucket slot
__device__ float4   b_pay [NB * BSLOTS];      // output payload per bucket slot
__device__ unsigned b_chunk[NCH];             // per-chunk totals (transient)
__device__ unsigned g_done;                   // phase-1 ticket (reset at exit)
__device__ unsigned g_done2;                  // phase-2 ticket (reset at exit)

__device__ __forceinline__ unsigned cell_of(unsigned idx) {
    unsigned z = idx >> 18, y = (idx >> 9) & 511u, x = idx & 511u;
    return ((z >> 3) << 12) | ((y >> 3) << 6) | (x >> 3);
}

// ---- kernel 1: stream volume; block-aggregated compact append + cell slots ----
__global__ void k_detect(const float* __restrict__ vol) {
    __shared__ uint2 s_cand[1024];
    __shared__ unsigned s_cnt, s_base;
    if (threadIdx.x == 0) s_cnt = 0u;
    __syncthreads();

    const float4* v4 = (const float4*)vol;
    unsigned tile = blockIdx.x * 2048u;
#pragma unroll
    for (int j = 0; j < 8; j++) {
        unsigned i = tile + j * 256u + threadIdx.x;
        float4 f = v4[i];
        unsigned base = i * 4u;
        float vv[4] = {f.x, f.y, f.z, f.w};
#pragma unroll
        for (int e = 0; e < 4; e++) {
            if (vv[e] > THRESH) {
                unsigned p = atomicAdd(&s_cnt, 1u);
                if (p < 1024u) s_cand[p] = make_uint2(base + (unsigned)e, __float_as_uint(vv[e]));
            }
        }
    }
    __syncthreads();
    unsigned cnt = min(s_cnt, 1024u);
    if (threadIdx.x == 0) s_base = atomicAdd(&g_ncand, cnt);
    __syncthreads();
    for (unsigned j = threadIdx.x; j < cnt; j += blockDim.x) {
        uint2 rec = s_cand[j];
        unsigned p = s_base + j;
        if (p < CAND_CAP) g_cand[p] = rec;
        unsigned c = cell_of(rec.x);
        unsigned slot = atomicAdd(&c_cnt[c], 1u);   // 65536 addrs: no contention
        if (slot < CSLOTS) c_data[c * CSLOTS + slot] = rec;
    }
}

// ---- kernel 2: verify 7^3 local max via cell probes; peaks -> bucket slots ----
// A defeating neighbor (> v > 0.997) is itself a candidate, so only candidate
// records in the <=8 overlapping cells need checking. Surviving peaks get the
// full centroid + reconstruction here (order-independent) and are deposited
// directly into their value-bucket's slot array (one atomic = slot + histogram).
__global__ void __launch_bounds__(256) k_verify_cent(const float* __restrict__ vol) {
    unsigned i = blockIdx.x * blockDim.x + threadIdx.x;
    unsigned n = min(g_ncand, (unsigned)CAND_CAP);
    if (i >= n) return;
    uint2 me = g_cand[i];
    unsigned idx = me.x;
    float v = __uint_as_float(me.y);
    int z = idx >> 18, y = (idx >> 9) & 511, x = idx & 511;

    int cz0 = max(z - 3, 0) >> 3, cz1 = min(z + 3, DD - 1) >> 3;
    int cy0 = max(y - 3, 0) >> 3, cy1 = min(y + 3, HH - 1) >> 3;
    int cx0 = max(x - 3, 0) >> 3, cx1 = min(x + 3, WW - 1) >> 3;
    bool peak = true;
    for (int cz = cz0; cz <= cz1 && peak; cz++)
    for (int cy = cy0; cy <= cy1 && peak; cy++)
    for (int cx = cx0; cx <= cx1 && peak; cx++) {
        unsigned c2 = ((unsigned)cz << 12) | ((unsigned)cy << 6) | (unsigned)cx;
        unsigned cn2 = min(c_cnt[c2], (unsigned)CSLOTS);
        unsigned b2 = c2 * CSLOTS;
        for (unsigned j = 0; j < cn2; j++) {
            uint2 r = c_data[b2 + j];
            if (__uint_as_float(r.y) > v) {
                int rz = r.x >> 18, ry = (r.x >> 9) & 511, rx = r.x & 511;
                if (abs(rz - z) <= 3 && abs(ry - y) <= 3 && abs(rx - x) <= 3) {
                    peak = false; break;
                }
            }
        }
    }
    if (!peak) return;

    // centroid over the 7^3 patch: each x-run covered by three aligned float4
    // loads from a = clamp((x-3)&~3, 0, 500), out-of-window weight-masked
    // (matches the reference's zero padding). dz loop NOT unrolled: 21 loads in
    // flight per iteration is already ample MLP; keeps register count low.
    int a = max(x - 3, 0) & ~3;
    if (a > WW - 12) a = WW - 12;
    float s0 = 0.f, sx = 0.f, sy = 0.f, sz = 0.f;
#pragma unroll 1
    for (int dz = -3; dz <= 3; dz++) {
        int zz = z + dz;
        if ((unsigned)zz >= (unsigned)DD) continue;
        const float* pz = vol + ((unsigned)zz << 18);
#pragma unroll
        for (int dy = -3; dy <= 3; dy++) {
            int yy = y + dy;
            if ((unsigned)yy >= (unsigned)HH) continue;
            const float* rp = pz + ((unsigned)yy << 9);
            float4 A = *(const float4*)(rp + a);
            float4 B = *(const float4*)(rp + a + 4);
            float4 C = *(const float4*)(rp + a + 8);
            float vals[12] = {A.x, A.y, A.z, A.w, B.x, B.y, B.z, B.w, C.x, C.y, C.z, C.w};
            float rs0 = 0.f, rsx = 0.f;
#pragma unroll
            for (int e = 0; e < 12; e++) {
                int dx = a + e - x;
                bool in = (dx >= -3) && (dx <= 3);
                float vv = in ? vals[e] : 0.f;
                rs0 += vv;
                rsx += vv * (float)dx;
            }
            s0 += rs0;
            sx += rsx;
            sy += rs0 * (float)dy;
            sz += rs0 * (float)dz;
        }
    }
    float inv  = 1.f / s0;
    float xrec = ((float)x + sx * inv - 255.5f) * 0.1f;
    float yrec = ((float)y + sy * inv - 255.5f) * 0.1f;
    float zrec = ((float)z + sz * inv + 0.5f) * 0.02f - 2.0f;

    // deposit into value-bucket slot (bucket index <-> exact float value,
    // since all peaks share the top 16 bits 0x3F7F)
    unsigned bucket = me.y & 0xFFFFu;
    unsigned slot = atomicAdd(&g_hist[bucket], 1u);
    if (slot < BSLOTS) {
        b_sidx[bucket * BSLOTS + slot] = idx;
        b_pay [bucket * BSLOTS + slot] = make_float4(xrec, yrec, zrec, v);
    }
}

// ---- kernel 3: fused rank = suffix scan + finalize + padding (grid-resident) --
// 64 blocks x 256 threads, all co-resident. Phase 1: per-chunk suffix scan with
// per-bucket offsets kept IN REGISTERS of the thread that will finalize those
// buckets. Spin-sync on a ticket. Phase 2: each block computes its own csuf from
// the 64 chunk totals, then thread t finalizes buckets t*4..t*4+3 (sort slots by
// voxel index = lax.top_k stable tie-break, write output rows), plus its share
// of zero-padding rows. All counters restored for graph replay.
__global__ void k_rank(float* __restrict__ out, float* __restrict__ validOut,
                       int writeValid) {
    __shared__ unsigned s_w[8];
    __shared__ unsigned s_chunk[NCH];
    int t = threadIdx.x;
    unsigned blk = blockIdx.x;
    unsigned base = blk * 1024u;

    // ---- phase 1: load counts (reset in place), local suffix scan ----
    unsigned h0 = g_hist[base + t*4 + 0];
    unsigned h1 = g_hist[base + t*4 + 1];
    unsigned h2 = g_hist[base + t*4 + 2];
    unsigned h3 = g_hist[base + t*4 + 3];
    if (h0) g_hist[base + t*4 + 0] = 0u;
    if (h1) g_hist[base + t*4 + 1] = 0u;
    if (h2) g_hist[base + t*4 + 2] = 0u;
    if (h3) g_hist[base + t*4 + 3] = 0u;
    // counter restoration folded in (independent stores)
#pragma unroll
    for (int j = 0; j < 4; j++) c_cnt[base + j * 256 + t] = 0u;
    if (blk == 0 && t == 0) g_ncand = 0u;

    unsigned sum4 = h0 + h1 + h2 + h3;
    unsigned v = sum4;
    int lane = t & 31, w = t >> 5;
#pragma unroll
    for (int d = 1; d < 32; d <<= 1) {
        unsigned o = __shfl_down_sync(0xFFFFFFFFu, v, d);
        if (lane + d < 32) v += o;
    }
    if (lane == 0) s_w[w] = v;
    __syncthreads();
    unsigned wafter = 0;
#pragma unroll
    for (int i = 0; i < 8; i++) if (i > w) wafter += s_w[i];
    unsigned run = wafter + (v - sum4);          // strictly-after, within chunk
    unsigned o3 = run; run += h3;
    unsigned o2 = run; run += h2;
    unsigned o1 = run; run += h1;
    unsigned o0 = run; run += h0;                // run == chunk total at t==0

    if (t == 0) {
        b_chunk[blk] = run;
        __threadfence();
        atomicAdd(&g_done, 1u);
        while (*((volatile unsigned*)&g_done) < (unsigned)NCH) __nanosleep(64);
    }
    __syncthreads();
    __threadfence();                              // see other blocks' b_chunk

    if (t < NCH) s_chunk[t] = *((volatile unsigned*)&b_chunk[t]);
    __syncthreads();

    unsigned csuf = 0, tot = 0;
#pragma unroll 1
    for (int i = 0; i < NCH; i++) {
        unsigned cv = s_chunk[i];
        tot += cv;
        if (i > (int)blk) csuf += cv;
    }
    unsigned total = min(tot, (unsigned)KPK);

    // ---- phase 2: finalize this thread's 4 buckets (offsets in registers) ----
    unsigned hh[4] = {h0, h1, h2, h3};
    unsigned oo[4] = {o0, o1, o2, o3};
#pragma unroll 1
    for (int j = 0; j < 4; j++) {
        unsigned craw = hh[j];
        if (craw == 0u) continue;
        unsigned b = base + (unsigned)(t * 4 + j);
        unsigned c = min(craw, (unsigned)BSLOTS);
        unsigned F = oo[j] + csuf;
        if (F >= (unsigned)KPK) continue;
        if (F + c > (unsigned)KPK) c = (unsigned)KPK - F;
        unsigned s = b * BSLOTS;

        if (c == 1u) {
            ((float4*)out)[F] = b_pay[s];
            if (writeValid) validOut[F] = 1.f;
            continue;
        }
        uint4  s4 = *((const uint4*)(b_sidx + s));
        float4 p0 = b_pay[s + 0];
        float4 p1 = b_pay[s + 1];
        if (c == 2u) {
            bool sw = s4.x > s4.y;                // ascending voxel index
            ((float4*)out)[F + 0] = sw ? p1 : p0;
            ((float4*)out)[F + 1] = sw ? p0 : p1;
            if (writeValid) { validOut[F] = 1.f; validOut[F + 1] = 1.f; }
            continue;
        }
        if (c <= 4u) {
            float4 pay[4];
            pay[0] = p0; pay[1] = p1;
            for (unsigned q = 2; q < c; q++) pay[q] = b_pay[s + q];
            unsigned idxv[4] = {s4.x, s4.y, s4.z, s4.w};
            unsigned ord[4]  = {0u, 1u, 2u, 3u};
            for (unsigned ii = 1; ii < c; ii++) {
                unsigned kv = idxv[ii], ko = ord[ii];
                int q = (int)ii - 1;
                while (q >= 0 && idxv[q] > kv) {
                    idxv[q + 1] = idxv[q]; ord[q + 1] = ord[q]; q--;
                }
                idxv[q + 1] = kv; ord[q + 1] = ko;
            }
            for (unsigned r = 0; r < c; r++) {
                ((float4*)out)[F + r] = pay[ord[r]];
                if (writeValid) validOut[F + r] = 1.f;
            }
            continue;
        }
        // rare tail: full-width sort
        unsigned idxv[BSLOTS];
        unsigned ord[BSLOTS];
        idxv[0] = s4.x; idxv[1] = s4.y; idxv[2] = s4.z; idxv[3] = s4.w;
        for (unsigned q = 4; q < c; q++) idxv[q] = b_sidx[s + q];
        for (unsigned q = 0; q < c; q++) ord[q] = q;
        for (unsigned ii = 1; ii < c; ii++) {
            unsigned kv = idxv[ii], ko = ord[ii];
            int q = (int)ii - 1;
            while (q >= 0 && idxv[q] > kv) {
                idxv[q + 1] = idxv[q]; ord[q + 1] = ord[q]; q--;
            }
            idxv[q + 1] = kv; ord[q + 1] = ko;
        }
        for (unsigned r = 0; r < c; r++) {
            ((float4*)out)[F + r] = b_pay[s + ord[r]];
            if (writeValid) validOut[F + r] = 1.f;
        }
    }

    // ---- zero-padding rows (row >= total), spread over all 16384 threads ----
    unsigned gt = blk * 256u + (unsigned)t;
#pragma unroll
    for (unsigned k = 0; k < KPK / (NCH * 256); k++) {
        unsigned row = gt + k * (NCH * 256);
        if (row >= total) {
            ((float4*)out)[row] = make_float4(0.f, 0.f, 0.f, 0.f);
            if (writeValid) validOut[row] = 0.f;
        }
    }

    // ---- exit ticket: last block resets both counters (replay-safe) ----
    __syncthreads();
    if (t == 0) {
        unsigned r = atomicAdd(&g_done2, 1u);
        if (r == (unsigned)(NCH - 1)) { g_done = 0u; g_done2 = 0u; }
    }
}

// ---------------- launch (3 kernels) ----------------
extern "C" void kernel_launch(void* const* d_in, const int* in_sizes, int n_in,
                              void* d_out, int out_size) {
    const float* vol = (const float*)d_in[0];
    float* out = (float*)d_out;
    int writeValid = (out_size >= KPK * 5) ? 1 : 0;
    float* validOut = out + (size_t)KPK * 4;

    k_detect<<<4096, 256>>>(vol);
    k_verify_cent<<<CAND_CAP / 256, 256>>>(vol);
    k_rank<<<NCH, 256>>>(out, validOut, writeValid);
}

// round 16
// speedup vs baseline: 1.2028x; 1.2028x over previous
#include <cuda_runtime.h>
#include <cuda_bf16.h>

#define DD 128
#define HH 512
#define WW 512
#define THRESH 0.997f
#define KPK 131072
#define NB  65536                 // value buckets AND spatial cells (16*64*64)
#define NCH 64                    // scan chunks of 1024 buckets
#define CSLOTS 16                 // per-cell candidate capacity (lambda~1.5 -> safe)
#define BSLOTS 16                 // per-bucket peak capacity (lambda~1.2 -> safe)
#define CAND_CAP (1<<18)          // 262144
#define NBLK_BUCKET (NB / 256)    // 256
#define NBLK_PAD    (KPK / 256)   // 512

// ------------- device scratch (static; all counters self-restore to 0) --------
__device__ unsigned c_cnt[NB];                // per-cell count   (zeroed by finalize)
__device__ uint2    c_data[NB * CSLOTS];      // (idx, valbits) per cell slot
__device__ unsigned g_ncand;                  // compact count    (zeroed by finalize)
__device__ uint2    g_cand[CAND_CAP];         // compact candidate list (idx, valbits)
__device__ unsigned g_hist[NB];               // per-bucket peak count (zeroed by finalize)
__device__ unsigned b_sidx[NB * BSLOTS];      // voxel idx per bucket slot
__device__ float4   b_pay [NB * BSLOTS];      // output payload per bucket slot
__device__ unsigned g_off[NB];                // within-chunk strictly-after offsets
__device__ unsigned b_chunk[NCH];
__device__ unsigned b_csuf[NCH];
__device__ unsigned g_done;                   // scan ticket (reset by last block)
__device__ unsigned g_total;                  // min(raw, KPK)

__device__ __forceinline__ unsigned cell_of(unsigned idx) {
    unsigned z = idx >> 18, y = (idx >> 9) & 511u, x = idx & 511u;
    return ((z >> 3) << 12) | ((y >> 3) << 6) | (x >> 3);
}

// ---- kernel 1: stream volume; block-aggregated compact append + cell slots ----
// 2048 blocks x 256 threads; 16 float4 per thread, loaded with __ldcs
// (evict-first streaming: the volume is single-use, keep it out of L2's way).
__global__ void k_detect(const float* __restrict__ vol) {
    __shared__ uint2 s_cand[2048];
    __shared__ unsigned s_cnt, s_base;
    if (threadIdx.x == 0) s_cnt = 0u;
    __syncthreads();

    const float4* v4 = (const float4*)vol;
    unsigned tile = blockIdx.x * 4096u;
#pragma unroll
    for (int j = 0; j < 16; j++) {
        unsigned i = tile + j * 256u + threadIdx.x;
        float4 f = __ldcs(&v4[i]);
        unsigned base = i * 4u;
        float vv[4] = {f.x, f.y, f.z, f.w};
#pragma unroll
        for (int e = 0; e < 4; e++) {
            if (vv[e] > THRESH) {
                unsigned p = atomicAdd(&s_cnt, 1u);
                if (p < 2048u) s_cand[p] = make_uint2(base + (unsigned)e, __float_as_uint(vv[e]));
            }
        }
    }
    __syncthreads();
    unsigned cnt = min(s_cnt, 2048u);
    if (threadIdx.x == 0) s_base = atomicAdd(&g_ncand, cnt);
    __syncthreads();
    for (unsigned j = threadIdx.x; j < cnt; j += blockDim.x) {
        uint2 rec = s_cand[j];
        unsigned p = s_base + j;
        if (p < CAND_CAP) g_cand[p] = rec;
        unsigned c = cell_of(rec.x);
        unsigned slot = atomicAdd(&c_cnt[c], 1u);   // 65536 addrs: no contention
        if (slot < CSLOTS) c_data[c * CSLOTS + slot] = rec;
    }
}

// ---- kernel 2: verify 7^3 local max via cell probes; peaks -> bucket slots ----
// A defeating neighbor (> v > 0.997) is itself a candidate, so only candidate
// records in the <=8 overlapping cells need checking. Surviving peaks get the
// full centroid + reconstruction here (order-independent) and are deposited
// directly into their value-bucket's slot array (one atomic = slot + histogram).
__global__ void k_verify_cent(const float* __restrict__ vol) {
    unsigned i = blockIdx.x * blockDim.x + threadIdx.x;
    unsigned n = min(g_ncand, (unsigned)CAND_CAP);
    if (i >= n) return;
    uint2 me = g_cand[i];
    unsigned idx = me.x;
    float v = __uint_as_float(me.y);
    int z = idx >> 18, y = (idx >> 9) & 511, x = idx & 511;

    int cz0 = max(z - 3, 0) >> 3, cz1 = min(z + 3, DD - 1) >> 3;
    int cy0 = max(y - 3, 0) >> 3, cy1 = min(y + 3, HH - 1) >> 3;
    int cx0 = max(x - 3, 0) >> 3, cx1 = min(x + 3, WW - 1) >> 3;
    bool peak = true;
    for (int cz = cz0; cz <= cz1 && peak; cz++)
    for (int cy = cy0; cy <= cy1 && peak; cy++)
    for (int cx = cx0; cx <= cx1 && peak; cx++) {
        unsigned c2 = ((unsigned)cz << 12) | ((unsigned)cy << 6) | (unsigned)cx;
        unsigned cn2 = min(c_cnt[c2], (unsigned)CSLOTS);
        unsigned b2 = c2 * CSLOTS;
        for (unsigned j = 0; j < cn2; j++) {
            uint2 r = c_data[b2 + j];
            if (__uint_as_float(r.y) > v) {
                int rz = r.x >> 18, ry = (r.x >> 9) & 511, rx = r.x & 511;
                if (abs(rz - z) <= 3 && abs(ry - y) <= 3 && abs(rx - x) <= 3) {
                    peak = false; break;
                }
            }
        }
    }
    if (!peak) return;

    // centroid over the 7^3 patch: each x-run covered by three aligned float4
    // loads from a = clamp((x-3)&~3, 0, 500), out-of-window weight-masked
    // (matches the reference's zero padding).
    int a = max(x - 3, 0) & ~3;
    if (a > WW - 12) a = WW - 12;
    float s0 = 0.f, sx = 0.f, sy = 0.f, sz = 0.f;
#pragma unroll
    for (int dz = -3; dz <= 3; dz++) {
        int zz = z + dz;
        if ((unsigned)zz >= (unsigned)DD) continue;
        const float* pz = vol + ((unsigned)zz << 18);
#pragma unroll
        for (int dy = -3; dy <= 3; dy++) {
            int yy = y + dy;
            if ((unsigned)yy >= (unsigned)HH) continue;
            const float* rp = pz + ((unsigned)yy << 9);
            float4 A = *(const float4*)(rp + a);
            float4 B = *(const float4*)(rp + a + 4);
            float4 C = *(const float4*)(rp + a + 8);
            float vals[12] = {A.x, A.y, A.z, A.w, B.x, B.y, B.z, B.w, C.x, C.y, C.z, C.w};
            float rs0 = 0.f, rsx = 0.f;
#pragma unroll
            for (int e = 0; e < 12; e++) {
                int dx = a + e - x;
                bool in = (dx >= -3) && (dx <= 3);
                float vv = in ? vals[e] : 0.f;
                rs0 += vv;
                rsx += vv * (float)dx;
            }
            s0 += rs0;
            sx += rsx;
            sy += rs0 * (float)dy;
            sz += rs0 * (float)dz;
        }
    }
    float inv  = 1.f / s0;
    float xrec = ((float)x + sx * inv - 255.5f) * 0.1f;
    float yrec = ((float)y + sy * inv - 255.5f) * 0.1f;
    float zrec = ((float)z + sz * inv + 0.5f) * 0.02f - 2.0f;

    // deposit into value-bucket slot (bucket index <-> exact float value,
    // since all peaks share the top 16 bits 0x3F7F)
    unsigned bucket = me.y & 0xFFFFu;
    unsigned slot = atomicAdd(&g_hist[bucket], 1u);
    if (slot < BSLOTS) {
        b_sidx[bucket * BSLOTS + slot] = idx;
        b_pay [bucket * BSLOTS + slot] = make_float4(xrec, yrec, zrec, v);
    }
}

// ---- kernel 3: fused two-level suffix (descending) scan over 65536 buckets ----
__global__ void k_scan() {
    __shared__ unsigned s_h[1024];
    __shared__ unsigned s_w[8];
    __shared__ unsigned s_last;
    int t = threadIdx.x;
    unsigned base = blockIdx.x * 1024u;
#pragma unroll
    for (int j = 0; j < 4; j++) s_h[j * 256 + t] = g_hist[base + j * 256 + t];
    __syncthreads();
    unsigned h0 = s_h[t*4+0], h1 = s_h[t*4+1], h2 = s_h[t*4+2], h3 = s_h[t*4+3];
    unsigned sum4 = h0 + h1 + h2 + h3;
    unsigned v = sum4;
    int lane = t & 31, w = t >> 5;
#pragma unroll
    for (int d = 1; d < 32; d <<= 1) {
        unsigned o = __shfl_down_sync(0xFFFFFFFFu, v, d);
        if (lane + d < 32) v += o;
    }
    if (lane == 0) s_w[w] = v;
    __syncthreads();
    unsigned wafter = 0;
    for (int i = w + 1; i < 8; i++) wafter += s_w[i];
    unsigned run = wafter + (v - sum4);          // strictly-after, within chunk
    unsigned o3 = run; run += h3;
    unsigned o2 = run; run += h2;
    unsigned o1 = run; run += h1;
    unsigned o0 = run; run += h0;
    g_off[base + t*4 + 0] = o0;
    g_off[base + t*4 + 1] = o1;
    g_off[base + t*4 + 2] = o2;
    g_off[base + t*4 + 3] = o3;
    if (t == 0) b_chunk[blockIdx.x] = run;       // chunk total

    if (t == 0) {
        __threadfence();
        s_last = (atomicAdd(&g_done, 1u) == NCH - 1u) ? 1u : 0u;
    }
    __syncthreads();
    if (s_last) {
        volatile unsigned* vc = (volatile unsigned*)b_chunk;
        if (t < NCH) {
            unsigned suf = 0;
            for (int i = t + 1; i < NCH; i++) suf += vc[i];
            b_csuf[t] = suf;
            if (t == 0) {
                g_total = min(suf + vc[0], (unsigned)KPK);
                g_done = 0u;                     // reset ticket for next replay
            }
        }
    }
}

// ---- kernel 4: finalize, role-split grid for occupancy ------------------------
// Blocks [0, NBLK_BUCKET): one thread per value bucket — all loads potentially
// needed for the dominant c<=2 case (hist, off, csuf, sidx quad, payloads 0-1)
// issued unconditionally before any branch. Blocks [NBLK_BUCKET, +NBLK_PAD):
// one thread per output row — pure streaming zero-padding for rows >= g_total.
__global__ void k_finalize(float* __restrict__ out, float* __restrict__ validOut,
                           int writeValid) {
    if (blockIdx.x >= (unsigned)NBLK_BUCKET) {
        // ---------- padding role: one row per thread ----------
        unsigned row = (blockIdx.x - NBLK_BUCKET) * blockDim.x + threadIdx.x;
        if (row < (unsigned)KPK && row >= g_total) {
            ((float4*)out)[row] = make_float4(0.f, 0.f, 0.f, 0.f);
            if (writeValid) validOut[row] = 0.f;
        }
        return;
    }

    // ---------- bucket role: one bucket per thread ----------
    unsigned b = blockIdx.x * blockDim.x + threadIdx.x;

    // issue every potentially-needed load up front (independent; MLP~7)
    unsigned craw = g_hist[b];
    unsigned off  = g_off[b];
    unsigned csuf = b_csuf[b >> 10];
    uint4  s4 = *((const uint4*)(b_sidx + b * BSLOTS));   // slots 0..3
    float4 p0 = b_pay[b * BSLOTS + 0];
    float4 p1 = b_pay[b * BSLOTS + 1];

    // counter restoration for graph replay — independent stores
    c_cnt[b] = 0u;
    if (craw != 0u) g_hist[b] = 0u;
    if (b == 0u) g_ncand = 0u;

    if (craw == 0u) return;
    unsigned c = min(craw, (unsigned)BSLOTS);
    unsigned F = off + csuf;
    if (F >= (unsigned)KPK) return;
    if (F + c > (unsigned)KPK) c = (unsigned)KPK - F;

    if (c == 1u) {                                   // ~2/3 of occupied buckets
        ((float4*)out)[F] = p0;
        if (writeValid) validOut[F] = 1.f;
        return;
    }
    if (c == 2u) {                                   // most of the rest
        bool sw = s4.x > s4.y;                       // ascending voxel index
        ((float4*)out)[F + 0] = sw ? p1 : p0;
        ((float4*)out)[F + 1] = sw ? p0 : p1;
        if (writeValid) { validOut[F] = 1.f; validOut[F + 1] = 1.f; }
        return;
    }

    unsigned s = b * BSLOTS;
    if (c <= 4u) {
        float4 pay[4];
        pay[0] = p0; pay[1] = p1;
        for (unsigned j = 2; j < c; j++) pay[j] = b_pay[s + j];
        unsigned idxv[4] = {s4.x, s4.y, s4.z, s4.w};
        unsigned ord[4]  = {0u, 1u, 2u, 3u};
        for (unsigned ii = 1; ii < c; ii++) {
            unsigned kv = idxv[ii], ko = ord[ii];
            int j = (int)ii - 1;
            while (j >= 0 && idxv[j] > kv) {
                idxv[j + 1] = idxv[j]; ord[j + 1] = ord[j]; j--;
            }
            idxv[j + 1] = kv; ord[j + 1] = ko;
        }
        for (unsigned r = 0; r < c; r++) {
            ((float4*)out)[F + r] = pay[ord[r]];
            if (writeValid) validOut[F + r] = 1.f;
        }
        return;
    }

    // rare tail (<1% of buckets): full-width sort
    unsigned idxv[BSLOTS];
    unsigned ord[BSLOTS];
    idxv[0] = s4.x; idxv[1] = s4.y; idxv[2] = s4.z; idxv[3] = s4.w;
    for (unsigned j = 4; j < c; j++) idxv[j] = b_sidx[s + j];
    for (unsigned j = 0; j < c; j++) ord[j] = j;
    for (unsigned ii = 1; ii < c; ii++) {
        unsigned kv = idxv[ii], ko = ord[ii];
        int j = (int)ii - 1;
        while (j >= 0 && idxv[j] > kv) {
            idxv[j + 1] = idxv[j]; ord[j + 1] = ord[j]; j--;
        }
        idxv[j + 1] = kv; ord[j + 1] = ko;
    }
    for (unsigned r = 0; r < c; r++) {
        ((float4*)out)[F + r] = b_pay[s + ord[r]];
        if (writeValid) validOut[F + r] = 1.f;
    }
}

// ---------------- launch (4 kernels) ----------------
extern "C" void kernel_launch(void* const* d_in, const int* in_sizes, int n_in,
                              void* d_out, int out_size) {
    const float* vol = (const float*)d_in[0];
    float* out = (float*)d_out;
    int writeValid = (out_size >= KPK * 5) ? 1 : 0;
    float* validOut = out + (size_t)KPK * 4;

    k_detect<<<2048, 256>>>(vol);
    k_verify_cent<<<CAND_CAP / 256, 256>>>(vol);
    k_scan<<<NCH, 256>>>();
    k_finalize<<<NBLK_BUCKET + NBLK_PAD, 256>>>(out, validOut, writeValid);
}